// round 5
// baseline (speedup 1.0000x reference)
#include <cuda_runtime.h>
#include <cstdint>

#define S_ROWS 50000
#define P_ROWS 10000
#define EMBED_DIM 64
#define CAP 3200000
#define T 256

// per-list by-col CSR scratch
__device__ int2 g_ent_a[CAP];    // (row, val_bits) grouped by col
__device__ int2 g_ent_ia[CAP];
__device__ int  g_rank_a[CAP];
__device__ int  g_rank_ia[CAP];
__device__ int  g_cnt_a[P_ROWS];     // zero at load; re-zeroed by scan_kernel
__device__ int  g_cnt_ia[P_ROWS];
__device__ int  g_ptr_a[P_ROWS + 1];
__device__ int  g_ptr_ia[P_ROWS + 1];

__device__ __forceinline__ void red_add_f2(float2* addr, float x, float y) {
    asm volatile("red.global.add.v2.f32 [%0], {%1, %2};"
                 :: "l"(addr), "f"(x), "f"(y) : "memory");
}

// launch 0: histogram on cols for both lists; atomicAdd return = within-col rank
__global__ void hist_all(const int* __restrict__ a_cols,
                         const int* __restrict__ ia_cols, int nnz, int eb) {
    int b = blockIdx.x;
    if (b < eb) {
        int e = b * T + threadIdx.x;
        if (e < nnz)
            g_rank_a[e] = atomicAdd(&g_cnt_a[__ldcs(&a_cols[e])], 1);
    } else {
        int e = (b - eb) * T + threadIdx.x;
        if (e < nnz)
            g_rank_ia[e] = atomicAdd(&g_cnt_ia[__ldcs(&ia_cols[e])], 1);
    }
}

// launch 1: exclusive scan of the two 10000-counter arrays (one block each).
// Also zeroes the counters so the next graph replay starts clean.
__global__ void scan_kernel() {
    int* cnt = blockIdx.x ? g_cnt_ia : g_cnt_a;
    int* ptr = blockIdx.x ? g_ptr_ia : g_ptr_a;
    int tid = threadIdx.x, lane = tid & 31, wid = tid >> 5;
    int base = tid * 10;

    int x[10];
    int tsum = 0;
    #pragma unroll
    for (int i = 0; i < 10; i++) {
        int idx = base + i;
        x[i] = (idx < P_ROWS) ? cnt[idx] : 0;
        tsum += x[i];
    }
    #pragma unroll
    for (int i = 0; i < 10; i++) {
        int idx = base + i;
        if (idx < P_ROWS) cnt[idx] = 0;
    }

    // warp inclusive scan of per-thread sums
    int v = tsum;
    #pragma unroll
    for (int o = 1; o < 32; o <<= 1) {
        int y = __shfl_up_sync(0xffffffffu, v, o);
        if (lane >= o) v += y;
    }
    __shared__ int wsum[32];
    if (lane == 31) wsum[wid] = v;
    __syncthreads();
    if (wid == 0) {
        int w = wsum[lane];
        #pragma unroll
        for (int o = 1; o < 32; o <<= 1) {
            int y = __shfl_up_sync(0xffffffffu, w, o);
            if (lane >= o) w += y;
        }
        wsum[lane] = w;
    }
    __syncthreads();

    int prefix = wid ? wsum[wid - 1] : 0;
    int run = prefix + (v - tsum);   // exclusive base for this thread
    #pragma unroll
    for (int i = 0; i < 10; i++) {
        int idx = base + i;
        if (idx < P_ROWS) ptr[idx] = run;
        run += x[i];
    }
    if (tid == 1023) ptr[P_ROWS] = run;  // total
}

// launch 2: atomic-free scatter into by-col buckets + zero the student output region
__global__ void scatter_zero(const int* __restrict__ a_rows,
                             const int* __restrict__ a_cols,
                             const float* __restrict__ a_vals,
                             const int* __restrict__ ia_rows,
                             const int* __restrict__ ia_cols,
                             const float* __restrict__ ia_vals,
                             float4* __restrict__ zero_dst, int n_zero_f4,
                             int nnz, int eb) {
    int b = blockIdx.x;
    if (b < eb) {
        int e = b * T + threadIdx.x;
        if (e < nnz) {
            int c = __ldcs(&a_cols[e]);
            int r = __ldcs(&a_rows[e]);
            int vb = __float_as_int(__ldcs(&a_vals[e]));
            g_ent_a[g_ptr_a[c] + __ldcs(&g_rank_a[e])] = make_int2(r, vb);
        }
    } else if (b < 2 * eb) {
        int e = (b - 2 * eb + eb) * T + threadIdx.x;
        if (e < nnz) {
            int c = __ldcs(&ia_cols[e]);
            int r = __ldcs(&ia_rows[e]);
            int vb = __float_as_int(__ldcs(&ia_vals[e]));
            g_ent_ia[g_ptr_ia[c] + __ldcs(&g_rank_ia[e])] = make_int2(r, vb);
        }
    } else {
        int i = (b - 2 * eb) * T + threadIdx.x;
        if (i < n_zero_f4) zero_dst[i] = make_float4(0.f, 0.f, 0.f, 0.f);
    }
}

// launch 3 (profiled slot): fused dual-direction reduce.
// One warp per col. Thread 'lane' owns float2 chunk 'lane' (64 floats = 32 float2).
// Per edge: gather s_emb row chunk (register-accumulate out_p[col]) and
// RED the scaled p_emb chunk into out_s[row].
__global__ void reduce_all(const float2* __restrict__ s_emb,
                           const float2* __restrict__ p_emb,
                           float2* __restrict__ out_sc,
                           float2* __restrict__ out_sic,
                           float2* __restrict__ out_pc,
                           float2* __restrict__ out_pic) {
    int b = blockIdx.x;
    const int2* ent; const int* ptr; float2* out_s; float2* out_p;
    if (b < 1250) { ent = g_ent_a;  ptr = g_ptr_a;  out_s = out_sc;  out_p = out_pc;  }
    else          { ent = g_ent_ia; ptr = g_ptr_ia; out_s = out_sic; out_p = out_pic; b -= 1250; }

    int wid = threadIdx.x >> 5;
    int lane = threadIdx.x & 31;
    int col = b * 8 + wid;            // 8 warps/block, 1250 blocks -> 10000 cols

    int start = ptr[col];
    int end   = ptr[col + 1];

    float2 pv = __ldg(&p_emb[(unsigned)col * 32 + lane]);
    float2 acc = make_float2(0.f, 0.f);

    for (int base = start; base < end; base += 32) {
        int e = base + lane;
        int2 pk = (e < end) ? __ldcs(&ent[e]) : make_int2(0, 0);
        int cnt = min(32, end - base);
        for (int j = 0; j < cnt; j++) {
            int   r = __shfl_sync(0xffffffffu, pk.x, j);
            float v = __int_as_float(__shfl_sync(0xffffffffu, pk.y, j));
            float2 sv = __ldg(&s_emb[(unsigned)r * 32 + lane]);
            acc.x = fmaf(v, sv.x, acc.x);
            acc.y = fmaf(v, sv.y, acc.y);
            red_add_f2(&out_s[(unsigned)r * 32 + lane], v * pv.x, v * pv.y);
        }
    }
    out_p[(unsigned)col * 32 + lane] = acc;
}

extern "C" void kernel_launch(void* const* d_in, const int* in_sizes, int n_in,
                              void* d_out, int out_size) {
    const float* student_embeds = (const float*)d_in[0];
    const float* problem_embeds = (const float*)d_in[1];
    const int*   a_rows  = (const int*)d_in[2];
    const int*   a_cols  = (const int*)d_in[3];
    const float* a_vals  = (const float*)d_in[4];
    const int*   ia_rows = (const int*)d_in[5];
    const int*   ia_cols = (const int*)d_in[6];
    const float* ia_vals = (const float*)d_in[7];

    float* out = (float*)d_out;
    const int nnz = in_sizes[2];

    float* out_student_c  = out;
    float* out_student_ic = out + S_ROWS * EMBED_DIM;
    float* out_problem_c  = out + 2 * S_ROWS * EMBED_DIM;
    float* out_problem_ic = out + 2 * S_ROWS * EMBED_DIM + P_ROWS * EMBED_DIM;

    int eb = (nnz + T - 1) / T;
    int n_zero_f4 = (2 * S_ROWS * EMBED_DIM) / 4;   // both student outputs
    int zb = (n_zero_f4 + T - 1) / T;

    hist_all<<<2 * eb, T>>>(a_cols, ia_cols, nnz, eb);
    scan_kernel<<<2, 1024>>>();
    scatter_zero<<<2 * eb + zb, T>>>(a_rows, a_cols, a_vals,
                                     ia_rows, ia_cols, ia_vals,
                                     (float4*)out, n_zero_f4, nnz, eb);
    reduce_all<<<2 * 1250, T>>>(
        (const float2*)student_embeds, (const float2*)problem_embeds,
        (float2*)out_student_c, (float2*)out_student_ic,
        (float2*)out_problem_c, (float2*)out_problem_ic);
}